// round 16
// baseline (speedup 1.0000x reference)
#include <cuda_runtime.h>
#include <cuda_bf16.h>
#include <cuda_fp16.h>
#include <cstdint>

#define BIGF 100000000.0f
// 1/(gamma*ln2) with gamma = 0.1, and gamma*ln2
#define INV_G_LN2 14.426950408889634f
#define G_LN2 0.06931471805599453f

__device__ __forceinline__ float fast_ex2(float x) {
    float y; asm("ex2.approx.ftz.f32 %0, %1;" : "=f"(y) : "f"(x)); return y;
}
__device__ __forceinline__ float fast_lg2(float x) {
    float y; asm("lg2.approx.ftz.f32 %0, %1;" : "=f"(y) : "f"(x)); return y;
}
__device__ __forceinline__ uint32_t smem_u32(const void* p) {
    uint32_t a;
    asm("{ .reg .u64 t; cvta.to.shared.u64 t, %1; cvt.u32.u64 %0, t; }" : "=r"(a) : "l"(p));
    return a;
}
__device__ __forceinline__ void cp16(uint32_t dst, const void* src) {
    asm volatile("cp.async.cg.shared.global [%0], [%1], 16;" :: "r"(dst), "l"(src) : "memory");
}
__device__ __forceinline__ void ldsm_x4(uint32_t* r, uint32_t addr) {
    asm volatile("ldmatrix.sync.aligned.m8n8.x4.shared.b16 {%0,%1,%2,%3}, [%4];"
                 : "=r"(r[0]), "=r"(r[1]), "=r"(r[2]), "=r"(r[3]) : "r"(addr));
}
__device__ __forceinline__ void mma_bf16(float* d, const uint32_t* a, uint32_t b0, uint32_t b1) {
    asm volatile(
        "mma.sync.aligned.m16n8k16.row.col.f32.bf16.bf16.f32 "
        "{%0,%1,%2,%3}, {%4,%5,%6,%7}, {%8,%9}, {%0,%1,%2,%3};\n"
        : "+f"(d[0]), "+f"(d[1]), "+f"(d[2]), "+f"(d[3])
        : "r"(a[0]), "r"(a[1]), "r"(a[2]), "r"(a[3]), "r"(b0), "r"(b1));
}
// swizzle for 64-byte rows: XOR chunk bits [5:4] with row bits (off bits [8:7])
__device__ __forceinline__ uint32_t swz(uint32_t off) { return off ^ ((off >> 3) & 0x30); }

// Scratch (static device allocations; no cudaMalloc anywhere)
__device__ __half g_D[50331648];           // 192 * 512 * 512, fp16
__device__ __nv_bfloat16 g_xb[8388608];    // bf16 copy of x
__device__ __nv_bfloat16 g_yb[8388608];    // bf16 copy of y
__device__ float g_xn[32768];
__device__ float g_yn[32768];
__device__ float g_dtw[192];

// ---------------------------------------------------------------------------
// Kernel 1: bf16 conversion + row squared-norms (norms FROM rounded values).
// ---------------------------------------------------------------------------
__global__ void norms_kernel(const float* __restrict__ x, const float* __restrict__ y) {
    int gw = (blockIdx.x * blockDim.x + threadIdx.x) >> 5;
    int lane = threadIdx.x & 31;
    if (gw >= 32768) return;
    const float* p = x + (size_t)gw * 256;
    const float* q = y + (size_t)gw * 256;
    float vx = 0.f, vy = 0.f;
#pragma unroll
    for (int u = 0; u < 8; ++u) {
        float a = p[lane + 32 * u];
        float b = q[lane + 32 * u];
        __nv_bfloat16 ab = __float2bfloat16(a);
        __nv_bfloat16 bb = __float2bfloat16(b);
        g_xb[(size_t)gw * 256 + lane + 32 * u] = ab;
        g_yb[(size_t)gw * 256 + lane + 32 * u] = bb;
        float af = __bfloat162float(ab), bf = __bfloat162float(bb);
        vx += af * af;
        vy += bf * bf;
    }
#pragma unroll
    for (int o = 16; o; o >>= 1) {
        vx += __shfl_xor_sync(0xffffffffu, vx, o);
        vy += __shfl_xor_sync(0xffffffffu, vy, o);
    }
    if (lane == 0) { g_xn[gw] = vx; g_yn[gw] = vy; }
}

// ---------------------------------------------------------------------------
// Kernel 2: sqdist via bf16 mma.sync m16n8k16 + ldmatrix + 3-stage cp.async
// pipeline (one __syncthreads per k-iteration). Unchanged from R15 (passing).
// ---------------------------------------------------------------------------
__global__ __launch_bounds__(256, 2) void sqdist_kernel() {
    __shared__ __align__(16) uint8_t smem[49152];

    int z = blockIdx.z;
    int m = z >> 6, b = z & 63;
    const __nv_bfloat16* A; const __nv_bfloat16* Bm; const float* an; const float* bn;
    if (m == 0)      { A = g_xb; Bm = g_yb; an = g_xn; bn = g_yn; }
    else if (m == 1) { A = g_xb; Bm = g_xb; an = g_xn; bn = g_xn; }
    else             { A = g_yb; Bm = g_yb; an = g_yn; bn = g_yn; }
    size_t boff = (size_t)b * 512 * 256;
    A += boff; Bm += boff; an += b * 512; bn += b * 512;
    __half* C = g_D + (size_t)z * 262144;

    int tid = threadIdx.x, warp = tid >> 5, lane = tid & 31;
    int wm = warp >> 2, wn = warp & 3;
    int gid = lane >> 2, tg = lane & 3;
    int rowBase = blockIdx.y * 128, colBase = blockIdx.x * 128;
    int warpRow = wm * 64, warpCol = wn * 32;

    uint32_t sbase = smem_u32(smem);

    float acc[4][4][4];
#pragma unroll
    for (int mt = 0; mt < 4; ++mt)
#pragma unroll
        for (int nt = 0; nt < 4; ++nt)
#pragma unroll
            for (int r = 0; r < 4; ++r) acc[mt][nt][r] = 0.f;

    int str = tid >> 2, stc = tid & 3;

#define STAGE(buf, it)                                                          \
    {                                                                           \
        int kb = (it) * 32;                                                     \
        _Pragma("unroll")                                                       \
        for (int h = 0; h < 2; ++h) {                                           \
            int r = str + 64 * h;                                               \
            uint32_t off = swz((uint32_t)(r * 64 + stc * 16));                  \
            cp16(sbase + (buf) * 16384 + off,                                   \
                 A + (size_t)(rowBase + r) * 256 + kb + stc * 8);               \
            cp16(sbase + (buf) * 16384 + 8192 + off,                            \
                 Bm + (size_t)(colBase + r) * 256 + kb + stc * 8);              \
        }                                                                       \
        asm volatile("cp.async.commit_group;" ::: "memory");                    \
    }

    STAGE(0, 0);
    STAGE(1, 1);

    for (int it = 0; it < 8; ++it) {
        if (it == 7) asm volatile("cp.async.wait_group 0;" ::: "memory");
        else         asm volatile("cp.async.wait_group 1;" ::: "memory");
        __syncthreads();

        int buf = it % 3;
        uint32_t sA = sbase + buf * 16384;
        uint32_t sB = sA + 8192;
#pragma unroll
        for (int ks = 0; ks < 2; ++ks) {
            uint32_t af[4][4];
#pragma unroll
            for (int mt = 0; mt < 4; ++mt) {
                int rowb = warpRow + mt * 16 + (lane & 15);
                ldsm_x4(af[mt], sA + swz((uint32_t)(rowb * 64 + ks * 32 + (lane >> 4) * 16)));
            }
            uint32_t bf[2][4];
#pragma unroll
            for (int nh = 0; nh < 2; ++nh) {
                int rowb = warpCol + nh * 16 + (lane & 15);
                ldsm_x4(bf[nh], sB + swz((uint32_t)(rowb * 64 + ks * 32 + (lane >> 4) * 16)));
            }
#pragma unroll
            for (int mt = 0; mt < 4; ++mt)
#pragma unroll
                for (int nt = 0; nt < 4; ++nt) {
                    int nh = nt >> 1, w = nt & 1;
                    mma_bf16(acc[mt][nt], af[mt], bf[nh][w], bf[nh][2 + w]);
                }
        }
        if (it < 6) STAGE((it + 2) % 3, it + 2);
    }

#pragma unroll
    for (int mt = 0; mt < 4; ++mt) {
        int r = rowBase + warpRow + mt * 16 + gid;
        float an0 = an[r], an1 = an[r + 8];
#pragma unroll
        for (int nt = 0; nt < 4; ++nt) {
            int c = colBase + warpCol + nt * 8 + 2 * tg;
            float bn0 = bn[c], bn1 = bn[c + 1];
            __half2 v0 = __floats2half2_rn(an0 + bn0 - 2.f * acc[mt][nt][0],
                                           an0 + bn1 - 2.f * acc[mt][nt][1]);
            __half2 v1 = __floats2half2_rn(an1 + bn0 - 2.f * acc[mt][nt][2],
                                           an1 + bn1 - 2.f * acc[mt][nt][3]);
            *(__half2*)&C[(size_t)r * 512 + c]       = v0;
            *(__half2*)&C[(size_t)(r + 8) * 512 + c] = v1;
        }
    }
#undef STAGE
}

// ---------------------------------------------------------------------------
// Kernel 3: soft-DTW DP. NEW: warp-uniform activity gating (thread t valid
// only for k in [t+2, t+513] -> warp w active only for k in [32w+2, 32w+544];
// ~47% of warp-steps skip all shfl/MUFU work) + 3-MUFU softmin (ex2 of the
// min is exactly 1). Barriers stay uniform. Edge parities init BIGF make the
// gated first/last reads line up with neighbor writes exactly.
// ---------------------------------------------------------------------------
__global__ __launch_bounds__(512, 2) void dtw_kernel() {
    __shared__ float band[512][17];
    __shared__ float e1[2][16];
    __shared__ float e2[2][16];

    int inst = blockIdx.x;
    const __half* __restrict__ D = g_D + (size_t)inst * 262144;
    int t = threadIdx.x;
    int lane = t & 31, warp = t >> 5;
    int wlo = warp * 32 + 2;      // first k with any valid lane in this warp
    int whi = warp * 32 + 544;    // last k with any valid lane

    if (t < 16) { e1[0][t] = BIGF; e1[1][t] = BIGF; e2[0][t] = BIGF; e2[1][t] = BIGF; }
    float r1 = BIGF, r2 = BIGF;
    __syncthreads();

    for (int kb = 2; kb <= 1024; kb += 16) {
        bool blockActive = (kb + 15 >= wlo) && (kb <= whi);
        if (blockActive) {
            int rbase = warp * 32;
#pragma unroll
            for (int it = 0; it < 16; ++it) {
                int row = rbase + it * 2 + (lane >> 4);
                int u = lane & 15;
                int c = kb - row - 2 + u;
                float v = 0.f;
                if ((unsigned)c < 512u) v = __half2float(__ldg(&D[row * 512 + c]));
                band[row][u] = v;
            }
        }
        __syncthreads();

        int kend = (kb + 16 > 1025) ? 1025 : (kb + 16);
        for (int k = kb; k < kend; ++k) {
            if (k >= wlo && k <= whi) {          // warp-uniform gate
                float up1 = __shfl_up_sync(0xffffffffu, r1, 1);
                float up2 = __shfl_up_sync(0xffffffffu, r2, 1);
                if (lane == 0) {
                    if (warp == 0) { up1 = BIGF; up2 = (k == 2) ? 0.f : BIGF; }
                    else {
                        int rb = (k + 1) & 1;
                        up1 = e1[rb][warp - 1];
                        up2 = e2[rb][warp - 1];
                    }
                }
                int jm1 = k - t - 2;
                bool valid = ((unsigned)jm1 < 512u);
                float d = band[t][k - kb];
                float lo = fminf(up1, up2), hi = fmaxf(up1, up2);
                float mn = fminf(lo, r1),  mid = fmaxf(lo, r1);
                float s = 1.0f + fast_ex2((mn - hi)  * INV_G_LN2)
                               + fast_ex2((mn - mid) * INV_G_LN2);
                float sm = mn - G_LN2 * fast_lg2(s);
                r2 = r1;
                r1 = valid ? d + sm : BIGF;
                if (lane == 31) {
                    int wb = k & 1;
                    e1[wb][warp] = r1;
                    e2[wb][warp] = r2;
                }
            }
            __syncthreads();
        }
    }
    if (t == 511) g_dtw[inst] = r1;   // R[512, 512]
}

// ---------------------------------------------------------------------------
// Kernel 4: out[b] = dtw_xy - 0.5*(dtw_xx + dtw_yy)
// ---------------------------------------------------------------------------
__global__ void combine_kernel(float* __restrict__ out) {
    int b = threadIdx.x;
    if (b < 64) out[b] = g_dtw[b] - 0.5f * (g_dtw[64 + b] + g_dtw[128 + b]);
}

extern "C" void kernel_launch(void* const* d_in, const int* in_sizes, int n_in,
                              void* d_out, int out_size) {
    const float* x = (const float*)d_in[0];
    const float* y = (const float*)d_in[1];
    float* out = (float*)d_out;

    norms_kernel<<<4096, 256>>>(x, y);
    dim3 g(4, 4, 192);
    sqdist_kernel<<<g, 256>>>();
    dtw_kernel<<<192, 512>>>();
    combine_kernel<<<1, 64>>>(out);
}